// round 4
// baseline (speedup 1.0000x reference)
#include <cuda_runtime.h>
#include <math.h>
#include <float.h>

#define B 256
#define N 2048
#define M 64
#define C 512
#define OUTD 198   // 3*M + 6

// Param scratch layout per batch (stride 208):
//  [0..63]   k (raw)
//  [64..127] e = sigmoid(o[70..133])
//  [128..191] a = o[134..197]
//  [192] beta  [193] g  [194] gamma  [195..197] s0,s1,s2  [198] ||k+eps||
#define P_STRIDE 208
__device__ float g_params[B * P_STRIDE];

__device__ __forceinline__ float softplus_f(float x) {
    return (x > 20.f) ? x : log1pf(expf(x));
}
__device__ __forceinline__ float sigmoid_f(float x) {
    return 1.f / (1.f + __expf(-x));
}

// ---------------------------------------------------------------------------
// Kernel 1: controller projection o = h @ W^T + b, activations, k-norm.
// Grid (128, 2): x = batch-pair (2 batches share each W read), y = output
// chunk: y==0 -> j in [0,70) (k + scalars), y==1 -> j in [70,198) (e, a).
// ---------------------------------------------------------------------------
__global__ void k_proj(const float* __restrict__ h,
                       const float* __restrict__ Wm,
                       const float* __restrict__ bias) {
    int b0 = blockIdx.x * 2;
    int by = blockIdx.y;
    __shared__ float sh[2][C];
    __shared__ float so[2][128];

    for (int i = threadIdx.x; i < 2 * C; i += 256)
        sh[i >> 9][i & (C - 1)] = h[(size_t)b0 * C + i];
    __syncthreads();

    int warp = threadIdx.x >> 5, lane = threadIdx.x & 31;
    int jbase = by ? 70 : 0;
    int jcount = by ? 128 : 70;

    for (int jj = warp; jj < jcount; jj += 8) {
        const float* wr = Wm + (size_t)(jbase + jj) * C;
        float a0 = 0.f, a1 = 0.f;
        #pragma unroll 8
        for (int c = lane; c < C; c += 32) {
            float wv = wr[c];
            a0 += wv * sh[0][c];
            a1 += wv * sh[1][c];
        }
        #pragma unroll
        for (int o = 16; o; o >>= 1) {
            a0 += __shfl_xor_sync(0xffffffffu, a0, o);
            a1 += __shfl_xor_sync(0xffffffffu, a1, o);
        }
        if (lane == 0) {
            float bv = bias[jbase + jj];
            so[0][jj] = a0 + bv;
            so[1][jj] = a1 + bv;
        }
    }
    __syncthreads();

    int t = threadIdx.x;
    if (by == 0) {
        if (t < 128) {
            int bb = t >> 6;
            g_params[(b0 + bb) * P_STRIDE + (t & 63)] = so[bb][t & 63];
        } else if (t == 128 || t == 129) {
            int bb = t - 128;
            float* p = g_params + (b0 + bb) * P_STRIDE;
            p[192] = softplus_f(so[bb][64]);          // beta
            p[193] = sigmoid_f(so[bb][65]);           // g
            p[194] = 1.f + softplus_f(so[bb][69]);    // gamma
            float s0 = so[bb][66], s1 = so[bb][67], s2 = so[bb][68];
            float mx = fmaxf(s0, fmaxf(s1, s2));
            float e0 = __expf(s0 - mx), e1 = __expf(s1 - mx), e2 = __expf(s2 - mx);
            float inv = 1.f / (e0 + e1 + e2);
            p[195] = e0 * inv; p[196] = e1 * inv; p[197] = e2 * inv;
        }
        if (warp < 2) {   // ||k + 1e-16|| per batch
            int bb = warp;
            float v0 = so[bb][lane] + 1e-16f;
            float v1 = so[bb][lane + 32] + 1e-16f;
            float acc = v0 * v0 + v1 * v1;
            #pragma unroll
            for (int o = 16; o; o >>= 1) acc += __shfl_xor_sync(0xffffffffu, acc, o);
            if (lane == 0) g_params[(b0 + bb) * P_STRIDE + 198] = sqrtf(acc);
        }
    } else {
        int bb = t >> 7, tt = t & 127;
        float* p = g_params + (b0 + bb) * P_STRIDE;
        if (tt < 64) p[64 + tt] = sigmoid_f(so[bb][tt]);
        else         p[128 + (tt - 64)] = so[bb][tt];
    }
}

// ---------------------------------------------------------------------------
// Kernel 2 (FUSED): one block per batch (512 threads).
//  Phase 1: stream memory rows -> content scores in smem (8 lanes/row).
//  Phase 2: softmax + gate + circular shift + sharpen -> w (smem + d_out).
//  Phase 3: re-read memory (mostly L2-resident from phase 1) -> erase/add
//           write with streaming stores.
// ---------------------------------------------------------------------------
__device__ __forceinline__ float blockReduce512(float v, float* red, bool is_max) {
    int lane = threadIdx.x & 31, wid = threadIdx.x >> 5;
    #pragma unroll
    for (int o = 16; o; o >>= 1) {
        float t = __shfl_xor_sync(0xffffffffu, v, o);
        v = is_max ? fmaxf(v, t) : (v + t);
    }
    if (lane == 0) red[wid] = v;
    __syncthreads();
    float r = (threadIdx.x < 16) ? red[threadIdx.x] : (is_max ? -FLT_MAX : 0.f);
    if (wid == 0) {
        #pragma unroll
        for (int o = 8; o; o >>= 1) {
            float t = __shfl_xor_sync(0xffffffffu, r, o);
            r = is_max ? fmaxf(r, t) : (r + t);
        }
        if (lane == 0) red[0] = r;
    }
    __syncthreads();
    float out = red[0];
    __syncthreads();
    return out;
}

__global__ void k_fused(const float* __restrict__ memory,
                        const float* __restrict__ w_prev,
                        float* __restrict__ w_out,
                        float* __restrict__ mem_out) {
    int b = blockIdx.x;
    int tid = threadIdx.x;
    int warp = tid >> 5, lane = tid & 31;

    __shared__ float s_sc[N];     // scores, then reused as sharpened u
    __shared__ float s_w[N];      // gated+shifted weights
    __shared__ float sk[64];      // k + 1e-16
    __shared__ float sea[128];    // e[0..63], a[64..127]
    __shared__ float ssc[7];      // beta,g,gamma,s0,s1,s2,knorm
    __shared__ float red[32];

    // ---- Phase 0: params ----
    if (tid < 64)        sk[tid] = g_params[b * P_STRIDE + tid] + 1e-16f;
    else if (tid < 192)  sea[tid - 64] = g_params[b * P_STRIDE + tid];
    else if (tid < 199)  ssc[tid - 192] = g_params[b * P_STRIDE + tid];
    __syncthreads();

    // ---- Phase 1: content scores. 8 lanes/row, 2 float4/lane. ----
    {
        int sub = lane >> 3;      // row within warp group (0..3)
        int q = lane & 7;         // chunk within row
        float4 k0 = ((const float4*)sk)[q * 2];
        float4 k1 = ((const float4*)sk)[q * 2 + 1];
        float beta = ssc[0], knorm = ssc[6];

        const float4* base = (const float4*)(memory + (size_t)b * N * M);
        // warp covers rows warp*4+sub + it*64; 32 iterations
        #pragma unroll 2
        for (int it = 0; it < 32; it++) {
            int row = it * 64 + warp * 4 + sub;
            const float4* mp = base + (size_t)row * 16 + q * 2;
            float4 m0 = mp[0];
            float4 m1 = mp[1];
            float x0 = m0.x + 1e-16f, x1 = m0.y + 1e-16f, x2 = m0.z + 1e-16f, x3 = m0.w + 1e-16f;
            float y0 = m1.x + 1e-16f, y1 = m1.y + 1e-16f, y2 = m1.z + 1e-16f, y3 = m1.w + 1e-16f;
            float dot = x0 * k0.x + x1 * k0.y + x2 * k0.z + x3 * k0.w
                      + y0 * k1.x + y1 * k1.y + y2 * k1.z + y3 * k1.w;
            float nrm = x0 * x0 + x1 * x1 + x2 * x2 + x3 * x3
                      + y0 * y0 + y1 * y1 + y2 * y2 + y3 * y3;
            #pragma unroll
            for (int o = 4; o; o >>= 1) {
                dot += __shfl_xor_sync(0xffffffffu, dot, o);
                nrm += __shfl_xor_sync(0xffffffffu, nrm, o);
            }
            if (q == 0) {
                float denom = fmaxf(sqrtf(nrm) * knorm, 1e-8f);
                s_sc[row] = beta * dot / denom;
            }
        }
    }
    __syncthreads();

    // ---- Phase 2: softmax + gate + shift + sharpen ----
    {
        float v[4];
        float mx = -FLT_MAX;
        #pragma unroll
        for (int i = 0; i < 4; i++) { v[i] = s_sc[tid + i * 512]; mx = fmaxf(mx, v[i]); }
        mx = blockReduce512(mx, red, true);

        float sum = 0.f;
        #pragma unroll
        for (int i = 0; i < 4; i++) { v[i] = __expf(v[i] - mx); sum += v[i]; }
        sum = blockReduce512(sum, red, false);
        float inv = 1.f / sum;

        float g = ssc[1];
        #pragma unroll
        for (int i = 0; i < 4; i++) {
            int idx = tid + i * 512;
            s_w[idx] = g * (v[i] * inv) + (1.f - g) * w_prev[(size_t)b * N + idx];
        }
        __syncthreads();

        float s0 = ssc[3], s1 = ssc[4], s2 = ssc[5], gamma = ssc[2];
        float u[4];
        float psum = 0.f;
        #pragma unroll
        for (int i = 0; i < 4; i++) {
            int idx = tid + i * 512;
            float wt = s_w[(idx + N - 1) & (N - 1)] * s0 + s_w[idx] * s1
                     + s_w[(idx + 1) & (N - 1)] * s2;
            float ws = __powf(wt, gamma);   // wt >= 0
            u[i] = ws; psum += ws;
        }
        psum = blockReduce512(psum, red, false);
        float invp = 1.f / (psum + 1e-16f);
        #pragma unroll
        for (int i = 0; i < 4; i++) {
            int idx = tid + i * 512;
            float wf = u[i] * invp;
            s_sc[idx] = wf;                        // final w, reuse s_sc
            w_out[(size_t)b * N + idx] = wf;
        }
    }
    __syncthreads();

    // ---- Phase 3: erase/add write. Re-read memory (L2-warm), stream out. ----
    {
        const float4* min4 = (const float4*)(memory + (size_t)b * N * M);
        float4* mout4 = (float4*)(mem_out + (size_t)b * N * M);
        int m4 = tid & 15;                          // fixed across iterations
        float4 e4 = ((const float4*)sea)[m4];
        float4 a4 = ((const float4*)(sea + 64))[m4];

        #pragma unroll 4
        for (int i = tid; i < N * M / 4; i += 512) {
            int row = i >> 4;
            float wv = s_sc[row];
            float4 m = __ldcs(min4 + i);
            float4 o;
            o.x = m.x * (1.f - wv * e4.x) + wv * a4.x;
            o.y = m.y * (1.f - wv * e4.y) + wv * a4.y;
            o.z = m.z * (1.f - wv * e4.z) + wv * a4.z;
            o.w = m.w * (1.f - wv * e4.w) + wv * a4.w;
            __stcs(mout4 + i, o);
        }
    }
}

// ---------------------------------------------------------------------------
extern "C" void kernel_launch(void* const* d_in, const int* in_sizes, int n_in,
                              void* d_out, int out_size) {
    const float* h      = (const float*)d_in[0];
    const float* w_prev = (const float*)d_in[1];
    const float* memory = (const float*)d_in[2];
    const float* Wm     = (const float*)d_in[3];
    const float* bias   = (const float*)d_in[4];

    float* w_out   = (float*)d_out;                     // [B, N]
    float* mem_out = (float*)d_out + (size_t)B * N;     // [B, N, M]

    k_proj<<<dim3(B / 2, 2), 256>>>(h, Wm, bias);
    k_fused<<<B, 512>>>(memory, w_prev, w_out, mem_out);
}

// round 5
// speedup vs baseline: 1.1743x; 1.1743x over previous
#include <cuda_runtime.h>
#include <math.h>
#include <float.h>

#define B 256
#define N 2048
#define M 64
#define C 512
#define OUTD 198   // 3*M + 6

// Param scratch layout per batch (stride 208):
//  [0..63]   k (raw)
//  [64..127] e = sigmoid(o[70..133])
//  [128..191] a = o[134..197]
//  [192] beta  [193] g  [194] gamma  [195..197] s0,s1,s2  [198] ||k+eps||
#define P_STRIDE 208
__device__ float g_params[B * P_STRIDE];

__device__ __forceinline__ float softplus_f(float x) {
    return (x > 20.f) ? x : log1pf(expf(x));
}
__device__ __forceinline__ float sigmoid_f(float x) {
    return 1.f / (1.f + __expf(-x));
}

// ---------------------------------------------------------------------------
// Kernel 1: controller projection o = h @ W^T + b (+ local activations).
// Grid (64, 3): x = batch-quad (4 batches share every W load), y = j-chunk:
//   y0: j in [0,64)    -> k (+ knorm, block-local)
//   y1: j in [64,134)  -> beta,g,s,gamma,e (all block-local activations)
//   y2: j in [134,198) -> a
// W L2 traffic: 64 quads x ~full W = 26 MB.
// ---------------------------------------------------------------------------
__global__ void k_proj(const float* __restrict__ h,
                       const float* __restrict__ Wm,
                       const float* __restrict__ bias) {
    int b0 = blockIdx.x * 4;
    int chunk = blockIdx.y;
    const int jbase_t[3]  = {0, 64, 134};
    const int jcount_t[3] = {64, 70, 64};
    int jbase = jbase_t[chunk], jcount = jcount_t[chunk];

    __shared__ float sh[4][C];
    __shared__ float so[4][72];

    for (int i = threadIdx.x; i < 4 * C; i += 256)
        sh[i >> 9][i & (C - 1)] = h[(size_t)b0 * C + i];
    __syncthreads();

    int warp = threadIdx.x >> 5, lane = threadIdx.x & 31;

    for (int jj = warp; jj < jcount; jj += 8) {
        const float* wr = Wm + (size_t)(jbase + jj) * C;
        float a0 = 0.f, a1 = 0.f, a2 = 0.f, a3 = 0.f;
        #pragma unroll 8
        for (int c = lane; c < C; c += 32) {
            float wv = wr[c];
            a0 += wv * sh[0][c];
            a1 += wv * sh[1][c];
            a2 += wv * sh[2][c];
            a3 += wv * sh[3][c];
        }
        #pragma unroll
        for (int o = 16; o; o >>= 1) {
            a0 += __shfl_xor_sync(0xffffffffu, a0, o);
            a1 += __shfl_xor_sync(0xffffffffu, a1, o);
            a2 += __shfl_xor_sync(0xffffffffu, a2, o);
            a3 += __shfl_xor_sync(0xffffffffu, a3, o);
        }
        if (lane == 0) {
            float bv = bias[jbase + jj];
            so[0][jj] = a0 + bv;
            so[1][jj] = a1 + bv;
            so[2][jj] = a2 + bv;
            so[3][jj] = a3 + bv;
        }
    }
    __syncthreads();

    int t = threadIdx.x;
    int bb = t >> 6, m = t & 63;
    float* p = g_params + (b0 + bb) * P_STRIDE;

    if (chunk == 0) {
        p[m] = so[bb][m];                           // k raw
        if (warp < 4) {                              // knorm per batch (warp=bb)
            float v0 = so[warp][lane] + 1e-16f;
            float v1 = so[warp][lane + 32] + 1e-16f;
            float acc = v0 * v0 + v1 * v1;
            #pragma unroll
            for (int o = 16; o; o >>= 1) acc += __shfl_xor_sync(0xffffffffu, acc, o);
            if (lane == 0) g_params[(b0 + warp) * P_STRIDE + 198] = sqrtf(acc);
        }
    } else if (chunk == 1) {
        // so[bb]: [0]=beta-pre [1]=g-pre [2..4]=s-pre [5]=gamma-pre [6..69]=e-pre
        p[64 + m] = sigmoid_f(so[bb][6 + m]);       // e
        if (t < 4) {
            float* pp = g_params + (b0 + t) * P_STRIDE;
            pp[192] = softplus_f(so[t][0]);         // beta
            pp[193] = sigmoid_f(so[t][1]);          // g
            pp[194] = 1.f + softplus_f(so[t][5]);   // gamma
            float s0 = so[t][2], s1 = so[t][3], s2 = so[t][4];
            float mx = fmaxf(s0, fmaxf(s1, s2));
            float e0 = __expf(s0 - mx), e1 = __expf(s1 - mx), e2 = __expf(s2 - mx);
            float inv = 1.f / (e0 + e1 + e2);
            pp[195] = e0 * inv; pp[196] = e1 * inv; pp[197] = e2 * inv;
        }
    } else {
        p[128 + m] = so[bb][m];                     // a
    }
}

// ---------------------------------------------------------------------------
// Kernel 2 (FUSED): one block per batch, 1024 threads, 2 blocks/SM.
//  Phase 1: stream memory rows -> content scores in smem (8 lanes/row).
//  Phase 2: softmax + gate + circular shift + sharpen -> w (smem + d_out).
//  Phase 3: re-read memory (partially L2-resident) -> erase/add write.
// ---------------------------------------------------------------------------
__device__ __forceinline__ float blockReduce1024(float v, float* red, bool is_max) {
    int lane = threadIdx.x & 31, wid = threadIdx.x >> 5;
    #pragma unroll
    for (int o = 16; o; o >>= 1) {
        float t = __shfl_xor_sync(0xffffffffu, v, o);
        v = is_max ? fmaxf(v, t) : (v + t);
    }
    if (lane == 0) red[wid] = v;
    __syncthreads();
    if (wid == 0) {
        float r = red[lane];
        #pragma unroll
        for (int o = 16; o; o >>= 1) {
            float t = __shfl_xor_sync(0xffffffffu, r, o);
            r = is_max ? fmaxf(r, t) : (r + t);
        }
        if (lane == 0) red[0] = r;
    }
    __syncthreads();
    float out = red[0];
    __syncthreads();
    return out;
}

__global__ void __launch_bounds__(1024, 2)
k_fused(const float* __restrict__ memory,
        const float* __restrict__ w_prev,
        float* __restrict__ w_out,
        float* __restrict__ mem_out) {
    int b = blockIdx.x;
    int tid = threadIdx.x;
    int warp = tid >> 5, lane = tid & 31;

    __shared__ float s_sc[N];     // scores, then reused as final w
    __shared__ float s_w[N];      // gated weights
    __shared__ float sk[64];      // k + 1e-16
    __shared__ float sea[128];    // e[0..63], a[64..127]
    __shared__ float ssc[7];      // beta,g,gamma,s0,s1,s2,knorm
    __shared__ float red[32];

    // ---- Phase 0: params ----
    if (tid < 64)        sk[tid] = g_params[b * P_STRIDE + tid] + 1e-16f;
    else if (tid < 192)  sea[tid - 64] = g_params[b * P_STRIDE + tid];
    else if (tid < 199)  ssc[tid - 192] = g_params[b * P_STRIDE + tid];
    __syncthreads();

    // ---- Phase 1: content scores. 8 lanes/row, 2 float4/lane. ----
    {
        int sub = lane >> 3;      // row within warp group (0..3)
        int q = lane & 7;         // chunk within row
        float4 k0 = ((const float4*)sk)[q * 2];
        float4 k1 = ((const float4*)sk)[q * 2 + 1];
        float beta = ssc[0], knorm = ssc[6];

        const float4* base = (const float4*)(memory + (size_t)b * N * M);
        // 32 warps x 4 rows = 128 rows/iter; 16 iterations.
        #pragma unroll 2
        for (int it = 0; it < 16; it++) {
            int row = it * 128 + warp * 4 + sub;
            const float4* mp = base + (size_t)row * 16 + q * 2;
            float4 m0 = mp[0];
            float4 m1 = mp[1];
            float x0 = m0.x + 1e-16f, x1 = m0.y + 1e-16f, x2 = m0.z + 1e-16f, x3 = m0.w + 1e-16f;
            float y0 = m1.x + 1e-16f, y1 = m1.y + 1e-16f, y2 = m1.z + 1e-16f, y3 = m1.w + 1e-16f;
            float dot = x0 * k0.x + x1 * k0.y + x2 * k0.z + x3 * k0.w
                      + y0 * k1.x + y1 * k1.y + y2 * k1.z + y3 * k1.w;
            float nrm = x0 * x0 + x1 * x1 + x2 * x2 + x3 * x3
                      + y0 * y0 + y1 * y1 + y2 * y2 + y3 * y3;
            #pragma unroll
            for (int o = 4; o; o >>= 1) {
                dot += __shfl_xor_sync(0xffffffffu, dot, o);
                nrm += __shfl_xor_sync(0xffffffffu, nrm, o);
            }
            if (q == 0) {
                float denom = fmaxf(sqrtf(nrm) * knorm, 1e-8f);
                s_sc[row] = beta * dot / denom;
            }
        }
    }
    __syncthreads();

    // ---- Phase 2: softmax + gate + shift + sharpen ----
    {
        float v[2];
        float mx = fmaxf(s_sc[tid], s_sc[tid + 1024]);
        v[0] = s_sc[tid]; v[1] = s_sc[tid + 1024];
        mx = blockReduce1024(mx, red, true);

        float sum = 0.f;
        #pragma unroll
        for (int i = 0; i < 2; i++) { v[i] = __expf(v[i] - mx); sum += v[i]; }
        sum = blockReduce1024(sum, red, false);
        float inv = 1.f / sum;

        float g = ssc[1];
        #pragma unroll
        for (int i = 0; i < 2; i++) {
            int idx = tid + i * 1024;
            s_w[idx] = g * (v[i] * inv) + (1.f - g) * w_prev[(size_t)b * N + idx];
        }
        __syncthreads();

        float s0 = ssc[3], s1 = ssc[4], s2 = ssc[5], gamma = ssc[2];
        float u[2];
        float psum = 0.f;
        #pragma unroll
        for (int i = 0; i < 2; i++) {
            int idx = tid + i * 1024;
            float wt = s_w[(idx + N - 1) & (N - 1)] * s0 + s_w[idx] * s1
                     + s_w[(idx + 1) & (N - 1)] * s2;
            float ws = __powf(wt, gamma);   // wt >= 0
            u[i] = ws; psum += ws;
        }
        psum = blockReduce1024(psum, red, false);
        float invp = 1.f / (psum + 1e-16f);
        #pragma unroll
        for (int i = 0; i < 2; i++) {
            int idx = tid + i * 1024;
            float wf = u[i] * invp;
            s_sc[idx] = wf;                        // final w, reuse s_sc
            w_out[(size_t)b * N + idx] = wf;
        }
    }
    __syncthreads();

    // ---- Phase 3: erase/add write. Re-read memory (L2-warm), stream out. ----
    {
        const float4* min4 = (const float4*)(memory + (size_t)b * N * M);
        float4* mout4 = (float4*)(mem_out + (size_t)b * N * M);
        int m4 = tid & 15;                          // fixed across iterations
        float4 e4 = ((const float4*)sea)[m4];
        float4 a4 = ((const float4*)(sea + 64))[m4];

        #pragma unroll 4
        for (int i = tid; i < N * M / 4; i += 1024) {
            int row = i >> 4;
            float wv = s_sc[row];
            float4 m = __ldcs(min4 + i);
            float4 o;
            o.x = m.x * (1.f - wv * e4.x) + wv * a4.x;
            o.y = m.y * (1.f - wv * e4.y) + wv * a4.y;
            o.z = m.z * (1.f - wv * e4.z) + wv * a4.z;
            o.w = m.w * (1.f - wv * e4.w) + wv * a4.w;
            __stcs(mout4 + i, o);
        }
    }
}

// ---------------------------------------------------------------------------
extern "C" void kernel_launch(void* const* d_in, const int* in_sizes, int n_in,
                              void* d_out, int out_size) {
    const float* h      = (const float*)d_in[0];
    const float* w_prev = (const float*)d_in[1];
    const float* memory = (const float*)d_in[2];
    const float* Wm     = (const float*)d_in[3];
    const float* bias   = (const float*)d_in[4];

    float* w_out   = (float*)d_out;                     // [B, N]
    float* mem_out = (float*)d_out + (size_t)B * N;     // [B, N, M]

    k_proj<<<dim3(64, 3), 256>>>(h, Wm, bias);
    k_fused<<<B, 1024>>>(memory, w_prev, w_out, mem_out);
}